// round 4
// baseline (speedup 1.0000x reference)
#include <cuda_runtime.h>

#define BB 4
#define NN 50000
#define DD 256
#define EE 800000
#define CAP 96
#define TAU_MIN_F 0.001f
#define MAX_CORR_F 0.15f
#define XPBD_ITERS_I 4

// Ping-pong point buffers (float4-padded). 6.4 MB.
__device__ float4 g_x[2][BB * NN];
// Per-edge-batch corrections: g_corr[b*EE + e]. 51.2 MB.
__device__ float4 g_corr[BB * EE];
// Bucketed adjacency: counts + (edge<<1 | is_dst) entries. 19.4 MB.
__device__ int g_counts[NN];
__device__ int g_entries[NN * CAP];

// ---------------------------------------------------------------------------
// Kernel 1: x_pred = keypoints + tau * (hand_tokens @ head_w + head_b)
// ---------------------------------------------------------------------------
__global__ void pred_kernel(const float* __restrict__ keypoints,
                            const float* __restrict__ timesteps,
                            const float* __restrict__ hand_tokens,
                            const float* __restrict__ head_w,
                            const float* __restrict__ head_b) {
    __shared__ float sw[DD * 3];
    int tid = threadIdx.x;
    for (int i = tid; i < DD * 3; i += blockDim.x) sw[i] = head_w[i];
    __syncthreads();

    int warp = (int)((blockIdx.x * (size_t)blockDim.x + tid) >> 5);
    int lane = tid & 31;
    if (warp >= BB * NN) return;

    const float4* hrow =
        reinterpret_cast<const float4*>(hand_tokens + (size_t)warp * DD);
    float4 a = hrow[lane];
    float4 c = hrow[lane + 32];

    float acc0 = 0.f, acc1 = 0.f, acc2 = 0.f;
    int d0 = lane * 4;
    {
        const float* w = &sw[d0 * 3];
        acc0 += a.x * w[0] + a.y * w[3] + a.z * w[6] + a.w * w[9];
        acc1 += a.x * w[1] + a.y * w[4] + a.z * w[7] + a.w * w[10];
        acc2 += a.x * w[2] + a.y * w[5] + a.z * w[8] + a.w * w[11];
    }
    {
        const float* w = &sw[(d0 + 128) * 3];
        acc0 += c.x * w[0] + c.y * w[3] + c.z * w[6] + c.w * w[9];
        acc1 += c.x * w[1] + c.y * w[4] + c.z * w[7] + c.w * w[10];
        acc2 += c.x * w[2] + c.y * w[5] + c.z * w[8] + c.w * w[11];
    }

#pragma unroll
    for (int off = 16; off > 0; off >>= 1) {
        acc0 += __shfl_xor_sync(0xFFFFFFFFu, acc0, off);
        acc1 += __shfl_xor_sync(0xFFFFFFFFu, acc1, off);
        acc2 += __shfl_xor_sync(0xFFFFFFFFu, acc2, off);
    }

    if (lane == 0) {
        int b = warp / NN;
        float tau = fmaxf(1.0f - timesteps[b], TAU_MIN_F);
        size_t o = 3 * (size_t)warp;
        g_x[0][warp] = make_float4(
            keypoints[o + 0] + tau * (acc0 + head_b[0]),
            keypoints[o + 1] + tau * (acc1 + head_b[1]),
            keypoints[o + 2] + tau * (acc2 + head_b[2]), 0.f);
    }
}

// ---------------------------------------------------------------------------
// Adjacency build (rebuilt every launch; deterministic topology, slot order
// may vary -> only fp summation order changes, well within tolerance).
// ---------------------------------------------------------------------------
__global__ void zero_counts_kernel() {
    int i = blockIdx.x * blockDim.x + threadIdx.x;
    if (i < NN) g_counts[i] = 0;
}

__global__ void fill_adj_kernel(const int* __restrict__ edge_index) {
    int e = blockIdx.x * blockDim.x + threadIdx.x;
    if (e >= EE) return;
    int s = edge_index[e];
    int d = edge_index[EE + e];
    int slot = atomicAdd(&g_counts[s], 1);
    if (slot < CAP) g_entries[s * CAP + slot] = (e << 1);
    slot = atomicAdd(&g_counts[d], 1);
    if (slot < CAP) g_entries[d * CAP + slot] = (e << 1) | 1;
}

// ---------------------------------------------------------------------------
// Phase A of each iteration: per-edge clipped correction (all 4 batches).
// MUFU-bound; position gathers hit L2.
// ---------------------------------------------------------------------------
__global__ void __launch_bounds__(256) corr_kernel(
    const int* __restrict__ edge_index, const float* __restrict__ rest,
    int cur) {
    int e = blockIdx.x * blockDim.x + threadIdx.x;
    if (e >= EE) return;
    int s = edge_index[e];
    int d = edge_index[EE + e];
    float L0 = rest[e];

#pragma unroll
    for (int b = 0; b < BB; b++) {
        float4 xs = g_x[cur][b * NN + s];
        float4 xd = g_x[cur][b * NN + d];
        float dx = xs.x - xd.x;
        float dy = xs.y - xd.y;
        float dz = xs.z - xd.z;
        float d2 = fmaf(dx, dx, fmaf(dy, dy, dz * dz)) + 1e-24f;
        float rinv = rsqrtf(d2);
        float dist = d2 * rinv;
        float f = (L0 - dist) * 0.5f * rinv;
        float cx = fminf(fmaxf(f * dx, -MAX_CORR_F), MAX_CORR_F);
        float cy = fminf(fmaxf(f * dy, -MAX_CORR_F), MAX_CORR_F);
        float cz = fminf(fmaxf(f * dz, -MAX_CORR_F), MAX_CORR_F);
        g_corr[b * EE + e] = make_float4(cx, cy, cz, 0.f);
    }
}

// ---------------------------------------------------------------------------
// Phase B: warp per (node, batch) gathers signed corrections; zero atomics.
// Fuses the Jacobi "x + delta" (no copy kernel) and, on the last iteration,
// the v_eff epilogue (writes d_out directly).
// ---------------------------------------------------------------------------
__global__ void __launch_bounds__(256) gather_kernel(
    int cur, int nxt, int last, const float* __restrict__ keypoints,
    const float* __restrict__ timesteps, float* __restrict__ out) {
    int wg = (int)((blockIdx.x * (size_t)blockDim.x + threadIdx.x) >> 5);
    if (wg >= NN * BB) return;
    int node = wg >> 2;        // 4 consecutive warps share a node (L1 reuse)
    int b = wg & 3;
    int lane = threadIdx.x & 31;

    int deg = min(g_counts[node], CAP);
    float sx = 0.f, sy = 0.f, sz = 0.f;
    for (int i = lane; i < deg; i += 32) {
        int ent = g_entries[node * CAP + i];
        float4 c = g_corr[b * EE + (ent >> 1)];
        float sgn = (ent & 1) ? -1.f : 1.f;
        sx = fmaf(sgn, c.x, sx);
        sy = fmaf(sgn, c.y, sy);
        sz = fmaf(sgn, c.z, sz);
    }
#pragma unroll
    for (int off = 16; off > 0; off >>= 1) {
        sx += __shfl_xor_sync(0xFFFFFFFFu, sx, off);
        sy += __shfl_xor_sync(0xFFFFFFFFu, sy, off);
        sz += __shfl_xor_sync(0xFFFFFFFFu, sz, off);
    }

    if (lane == 0) {
        int idx = b * NN + node;
        float4 xc = g_x[cur][idx];
        float nx = xc.x + sx;
        float ny = xc.y + sy;
        float nz = xc.z + sz;
        if (!last) {
            g_x[nxt][idx] = make_float4(nx, ny, nz, 0.f);
        } else {
            float tau = fmaxf(1.0f - timesteps[b], TAU_MIN_F);
            size_t o = 3 * (size_t)idx;
            out[o + 0] = (nx - keypoints[o + 0]) / tau;
            out[o + 1] = (ny - keypoints[o + 1]) / tau;
            out[o + 2] = (nz - keypoints[o + 2]) / tau;
        }
    }
}

extern "C" void kernel_launch(void* const* d_in, const int* in_sizes, int n_in,
                              void* d_out, int out_size) {
    const float* keypoints = (const float*)d_in[0];
    const float* timesteps = (const float*)d_in[1];
    const float* hand_tokens = (const float*)d_in[2];
    const float* head_w = (const float*)d_in[3];
    const float* head_b = (const float*)d_in[4];
    const int* edge_index = (const int*)d_in[5];
    const float* rest = (const float*)d_in[6];
    float* out = (float*)d_out;

    const int rows = BB * NN;  // 200000

    // Phase 1: prediction head (warp per row)
    {
        long long threads = (long long)rows * 32;
        pred_kernel<<<(int)((threads + 255) / 256), 256>>>(
            keypoints, timesteps, hand_tokens, head_w, head_b);
    }

    // Adjacency build (overlaps nothing, but cheap)
    zero_counts_kernel<<<(NN + 255) / 256, 256>>>();
    fill_adj_kernel<<<(EE + 255) / 256, 256>>>(edge_index);

    // Phase 2: XPBD Jacobi iterations, two-phase (corr -> gather)
    int cur = 0;
    for (int it = 0; it < XPBD_ITERS_I; it++) {
        int nxt = cur ^ 1;
        int last = (it == XPBD_ITERS_I - 1);
        corr_kernel<<<(EE + 255) / 256, 256>>>(edge_index, rest, cur);
        {
            long long threads = (long long)rows * 32;
            gather_kernel<<<(int)((threads + 255) / 256), 256>>>(
                cur, nxt, last, keypoints, timesteps, out);
        }
        cur = nxt;
    }
}

// round 7
// speedup vs baseline: 2.0224x; 2.0224x over previous
#include <cuda_runtime.h>

#define BB 4
#define NN 50000
#define DD 256
#define EE 800000
#define TAU_MIN_F 0.001f
#define MAX_CORR_F 0.15f
#define XPBD_ITERS_I 4

// Node-major packed positions: x[buf][node][batch][xyz]
// 12 floats (48 B) per node, 16B-aligned blocks. 2 * 2.4 MB = 4.8 MB.
#define XN (NN * 12)
__device__ __align__(16) float g_x[2][XN];

// ---------------------------------------------------------------------------
// Kernel 1: x_pred = keypoints + tau * (hand_tokens @ head_w + head_b)
// warp-per-(b,node) row; writes BOTH ping-pong buffers (pre-copies iter 0).
// ---------------------------------------------------------------------------
__global__ void pred_kernel(const float* __restrict__ keypoints,
                            const float* __restrict__ timesteps,
                            const float* __restrict__ hand_tokens,
                            const float* __restrict__ head_w,
                            const float* __restrict__ head_b) {
    __shared__ float sw[DD * 3];
    int tid = threadIdx.x;
    for (int i = tid; i < DD * 3; i += blockDim.x) sw[i] = head_w[i];
    __syncthreads();

    int row = (int)((blockIdx.x * (size_t)blockDim.x + tid) >> 5);
    int lane = tid & 31;
    if (row >= BB * NN) return;

    const float4* hrow =
        reinterpret_cast<const float4*>(hand_tokens + (size_t)row * DD);
    float4 a = hrow[lane];
    float4 c = hrow[lane + 32];

    float acc0 = 0.f, acc1 = 0.f, acc2 = 0.f;
    int d0 = lane * 4;
    {
        const float* w = &sw[d0 * 3];
        acc0 += a.x * w[0] + a.y * w[3] + a.z * w[6] + a.w * w[9];
        acc1 += a.x * w[1] + a.y * w[4] + a.z * w[7] + a.w * w[10];
        acc2 += a.x * w[2] + a.y * w[5] + a.z * w[8] + a.w * w[11];
    }
    {
        const float* w = &sw[(d0 + 128) * 3];
        acc0 += c.x * w[0] + c.y * w[3] + c.z * w[6] + c.w * w[9];
        acc1 += c.x * w[1] + c.y * w[4] + c.z * w[7] + c.w * w[10];
        acc2 += c.x * w[2] + c.y * w[5] + c.z * w[8] + c.w * w[11];
    }

#pragma unroll
    for (int off = 16; off > 0; off >>= 1) {
        acc0 += __shfl_xor_sync(0xFFFFFFFFu, acc0, off);
        acc1 += __shfl_xor_sync(0xFFFFFFFFu, acc1, off);
        acc2 += __shfl_xor_sync(0xFFFFFFFFu, acc2, off);
    }

    if (lane == 0) {
        int b = row / NN;
        int node = row - b * NN;
        float tau = fmaxf(1.0f - timesteps[b], TAU_MIN_F);
        size_t o = 3 * (size_t)row;
        float px = keypoints[o + 0] + tau * (acc0 + head_b[0]);
        float py = keypoints[o + 1] + tau * (acc1 + head_b[1]);
        float pz = keypoints[o + 2] + tau * (acc2 + head_b[2]);
        int base = node * 12 + b * 3;
        g_x[0][base + 0] = px;
        g_x[0][base + 1] = py;
        g_x[0][base + 2] = pz;
        g_x[1][base + 0] = px;  // pre-copy for iteration 0's scatter target
        g_x[1][base + 1] = py;
        g_x[1][base + 2] = pz;
    }
}

// ---------------------------------------------------------------------------
// Kernel 2: one XPBD Jacobi iteration. Thread per edge; 4 batches' packed
// corrections per endpoint = 12 contiguous words = 3 fully-used v4 REDs.
// ---------------------------------------------------------------------------
__device__ __forceinline__ void red_add_v4(const float* ptr, float a, float b,
                                           float c, float d) {
    asm volatile("red.global.add.v4.f32 [%0], {%1, %2, %3, %4};"
                 :: "l"(ptr), "f"(a), "f"(b), "f"(c), "f"(d)
                 : "memory");
}

__global__ void __launch_bounds__(256) edge_kernel(
    const int* __restrict__ edge_index, const float* __restrict__ rest,
    int cur, int nxt) {
    int e = blockIdx.x * blockDim.x + threadIdx.x;
    if (e >= EE) return;
    int s = edge_index[e];
    int d = edge_index[EE + e];
    float L0 = rest[e];

    const float4* S4 =
        reinterpret_cast<const float4*>(&g_x[cur][s * 12]);
    const float4* D4 =
        reinterpret_cast<const float4*>(&g_x[cur][d * 12]);
    float S[12], D[12], C[12];
#pragma unroll
    for (int k = 0; k < 3; k++) {
        reinterpret_cast<float4*>(S)[k] = S4[k];
        reinterpret_cast<float4*>(D)[k] = D4[k];
    }

#pragma unroll
    for (int b = 0; b < BB; b++) {
        float dx = S[b * 3 + 0] - D[b * 3 + 0];
        float dy = S[b * 3 + 1] - D[b * 3 + 1];
        float dz = S[b * 3 + 2] - D[b * 3 + 2];
        float d2 = fmaf(dx, dx, fmaf(dy, dy, dz * dz)) + 1e-24f;
        float rinv = rsqrtf(d2);
        float dist = d2 * rinv;
        float f = (L0 - dist) * 0.5f * rinv;
        C[b * 3 + 0] = fminf(fmaxf(f * dx, -MAX_CORR_F), MAX_CORR_F);
        C[b * 3 + 1] = fminf(fmaxf(f * dy, -MAX_CORR_F), MAX_CORR_F);
        C[b * 3 + 2] = fminf(fmaxf(f * dz, -MAX_CORR_F), MAX_CORR_F);
    }

    const float* outS = &g_x[nxt][s * 12];
    const float* outD = &g_x[nxt][d * 12];
    red_add_v4(outS + 0, C[0], C[1], C[2], C[3]);
    red_add_v4(outS + 4, C[4], C[5], C[6], C[7]);
    red_add_v4(outS + 8, C[8], C[9], C[10], C[11]);
    red_add_v4(outD + 0, -C[0], -C[1], -C[2], -C[3]);
    red_add_v4(outD + 4, -C[4], -C[5], -C[6], -C[7]);
    red_add_v4(outD + 8, -C[8], -C[9], -C[10], -C[11]);
}

// ---------------------------------------------------------------------------
// Kernel 3: v_eff = (x_corrected - keypoints) / tau
// ---------------------------------------------------------------------------
__global__ void final_kernel(const float* __restrict__ keypoints,
                             const float* __restrict__ timesteps,
                             float* __restrict__ out, int cur) {
    int i = blockIdx.x * blockDim.x + threadIdx.x;
    if (i >= BB * NN) return;
    int b = i / NN;
    int node = i - b * NN;
    float tau = fmaxf(1.0f - timesteps[b], TAU_MIN_F);
    int base = node * 12 + b * 3;
    size_t o = 3 * (size_t)i;
    out[o + 0] = (g_x[cur][base + 0] - keypoints[o + 0]) / tau;
    out[o + 1] = (g_x[cur][base + 1] - keypoints[o + 1]) / tau;
    out[o + 2] = (g_x[cur][base + 2] - keypoints[o + 2]) / tau;
}

extern "C" void kernel_launch(void* const* d_in, const int* in_sizes, int n_in,
                              void* d_out, int out_size) {
    const float* keypoints = (const float*)d_in[0];
    const float* timesteps = (const float*)d_in[1];
    const float* hand_tokens = (const float*)d_in[2];
    const float* head_w = (const float*)d_in[3];
    const float* head_b = (const float*)d_in[4];
    const int* edge_index = (const int*)d_in[5];
    const float* rest = (const float*)d_in[6];
    float* out = (float*)d_out;

    const int rows = BB * NN;  // 200000

    float* x_base = nullptr;
    cudaGetSymbolAddress((void**)&x_base, g_x);

    // Phase 1: prediction head (writes both ping-pong buffers)
    {
        long long threads = (long long)rows * 32;
        pred_kernel<<<(int)((threads + 255) / 256), 256>>>(
            keypoints, timesteps, hand_tokens, head_w, head_b);
    }

    // Phase 2: XPBD Jacobi iterations (scatter with packed v4 REDs)
    int cur = 0;
    for (int it = 0; it < XPBD_ITERS_I; it++) {
        int nxt = cur ^ 1;
        if (it > 0) {
            // x_next := x_cur  (iteration 0 was pre-seeded by pred_kernel)
            cudaMemcpyAsync(x_base + (size_t)nxt * XN,
                            x_base + (size_t)cur * XN, XN * sizeof(float),
                            cudaMemcpyDeviceToDevice);
        }
        edge_kernel<<<(EE + 255) / 256, 256>>>(edge_index, rest, cur, nxt);
        cur = nxt;
    }

    // Phase 3: effective velocity
    final_kernel<<<(rows + 255) / 256, 256>>>(keypoints, timesteps, out, cur);
}